// round 7
// baseline (speedup 1.0000x reference)
#include <cuda_runtime.h>
#include <cstdint>

#define D         64
#define EDGE_DIM  16
#define MSG_IN    144
#define UPD_IN    128
#define MAXN      50000
#define MAXE      800000
#define SCAN_B    1024

// ---------------- scratch (device globals; no allocation allowed) ----------------
__device__ __align__(256) float g_x[MAXN * D];
__device__ __align__(256) float g_P[MAXN * D];   // x @ W_i + msg_b  (dst side)
__device__ __align__(256) float g_Q[MAXN * D];   // x @ W_j          (src side)
__device__ __align__(256) float g_agg[MAXN * D];
__device__ int g_ssrc[MAXE];     // src, sorted by dst
__device__ int g_sdst[MAXE];     // dst, sorted (ascending groups)
__device__ int g_eord[MAXE];     // original edge id, sorted by dst
__device__ int g_cnt[MAXN];      // per-dst degree
__device__ int g_incl[MAXN];     // inclusive scan within blocks
__device__ int g_pos[MAXN];      // running scatter cursor (starts at excl prefix)
__device__ int g_bsum[64];
__device__ int g_bsumx[64];
__device__ int g_is64;

typedef unsigned long long u64;

// ---------------- packed f32x2 helpers ----------------
__device__ __forceinline__ u64 pack2(float lo, float hi) {
    u64 r; asm("mov.b64 %0, {%1,%2};" : "=l"(r) : "f"(lo), "f"(hi)); return r;
}
__device__ __forceinline__ void fma2(u64& acc, u64 a, u64 b) {
    asm("fma.rn.f32x2 %0, %1, %2, %0;" : "+l"(acc) : "l"(a), "l"(b));
}
__device__ __forceinline__ u64 add2(u64 a, u64 b) {
    u64 r; asm("add.rn.f32x2 %0, %1, %2;" : "=l"(r) : "l"(a), "l"(b)); return r;
}
__device__ __forceinline__ void unpack2(u64 v, float& lo, float& hi) {
    asm("mov.b64 {%0,%1}, %2;" : "=f"(lo), "=f"(hi) : "l"(v));
}

// ---------------- dtype sniffing ----------------
__global__ void detect_kernel(const unsigned int* __restrict__ idx) {
    __shared__ unsigned int acc[256];
    unsigned int v = 0;
    for (int i = threadIdx.x; i < 2048; i += 256) v |= idx[2 * i + 1];
    acc[threadIdx.x] = v;
    __syncthreads();
    for (int s = 128; s > 0; s >>= 1) {
        if (threadIdx.x < s) acc[threadIdx.x] |= acc[threadIdx.x + s];
        __syncthreads();
    }
    if (threadIdx.x == 0) g_is64 = (acc[0] == 0u) ? 1 : 0;
}

// ---------------- zero counters ----------------
__global__ void zero_cnt_kernel(int N) {
    int i = blockIdx.x * 256 + threadIdx.x;
    if (i < N) g_cnt[i] = 0;
    if (blockIdx.x == 0 && threadIdx.x < 64) { g_bsum[threadIdx.x] = 0; }
}

// ---------------- histogram of dst (also reads indices in either width) ----------------
__global__ void hist_kernel(const void* __restrict__ eidx, int E) {
    int i = blockIdx.x * 256 + threadIdx.x;
    if (i >= E) return;
    int dst;
    if (g_is64) dst = (int)reinterpret_cast<const long long*>(eidx)[(size_t)E + i];
    else        dst = reinterpret_cast<const int*>(eidx)[E + i];
    atomicAdd(&g_cnt[dst], 1);
}

// ---------------- scan stage 1: per-block inclusive scan ----------------
__global__ void scan1_kernel(int N) {
    __shared__ int s[SCAN_B];
    int tid = threadIdx.x;
    int i = blockIdx.x * SCAN_B + tid;
    int v = (i < N) ? g_cnt[i] : 0;
    s[tid] = v;
    __syncthreads();
    for (int off = 1; off < SCAN_B; off <<= 1) {
        int t = (tid >= off) ? s[tid - off] : 0;
        __syncthreads();
        s[tid] += t;
        __syncthreads();
    }
    if (i < N) g_incl[i] = s[tid];
    if (tid == SCAN_B - 1) g_bsum[blockIdx.x] = s[tid];
}

// ---------------- scan stage 2: exclusive scan of block sums (1 block) ----------------
__global__ void scan2_kernel(int nb) {
    __shared__ int s[64];
    int tid = threadIdx.x;
    s[tid] = (tid < nb) ? g_bsum[tid] : 0;
    __syncthreads();
    if (tid == 0) {
        int run = 0;
        for (int b = 0; b < nb; b++) { g_bsumx[b] = run; run += s[b]; }
    }
}

// ---------------- scan stage 3: start offsets into g_pos ----------------
__global__ void scan3_kernel(int N) {
    int i = blockIdx.x * 256 + threadIdx.x;
    if (i < N) g_pos[i] = g_incl[i] + g_bsumx[i / SCAN_B] - g_cnt[i];
}

// ---------------- scatter: build dst-sorted edge arrays ----------------
__global__ void scatter_kernel(const void* __restrict__ eidx, int E) {
    int i = blockIdx.x * 256 + threadIdx.x;
    if (i >= E) return;
    int src, dst;
    if (g_is64) {
        const long long* p = reinterpret_cast<const long long*>(eidx);
        src = (int)p[i];
        dst = (int)p[(size_t)E + i];
    } else {
        const int* p = reinterpret_cast<const int*>(eidx);
        src = p[i];
        dst = p[E + i];
    }
    int pos = atomicAdd(&g_pos[dst], 1);
    g_ssrc[pos] = src;
    g_sdst[pos] = dst;
    g_eord[pos] = i;
}

// ---------------- P/Q precompute (1 thread/node, 64 accumulators; zeroes agg) ----------------
__global__ void pq_kernel(const float* __restrict__ xin,
                          const float* __restrict__ msg_w,
                          const float* __restrict__ msg_b,
                          int l, int N) {
    __shared__ __align__(16) float ws[64 * D];   // 16 KB
    __shared__ __align__(16) float bs[D];
    const int half = blockIdx.y;
    const float* x_src = xin ? xin : g_x;
    const float* W = msg_w + (size_t)l * MSG_IN * D + (size_t)half * 64 * D;
    for (int i = threadIdx.x; i < 64 * D; i += 256) ws[i] = W[i];
    if (threadIdx.x < D) bs[threadIdx.x] = half ? 0.f : msg_b[l * D + threadIdx.x];
    __syncthreads();

    int v = blockIdx.x * 256 + threadIdx.x;
    if (v >= N) return;

    if (half == 0) {   // zero agg rows for this layer (edge kernel follows in-stream)
        float4 z = make_float4(0.f, 0.f, 0.f, 0.f);
        float4* ap = reinterpret_cast<float4*>(g_agg + (size_t)v * D);
#pragma unroll
        for (int j = 0; j < 16; j++) ap[j] = z;
    }

    u64 acc[32];
    const u64* bp = reinterpret_cast<const u64*>(bs);
#pragma unroll
    for (int j = 0; j < 32; j++) acc[j] = bp[j];

    const float4* xr = reinterpret_cast<const float4*>(x_src + (size_t)v * D);
    for (int k4 = 0; k4 < 16; k4++) {
        float4 xv = xr[k4];
#pragma unroll
        for (int c = 0; c < 4; c++) {
            float xs = (c == 0) ? xv.x : (c == 1) ? xv.y : (c == 2) ? xv.z : xv.w;
            u64 a = pack2(xs, xs);
            const ulonglong2* wr = reinterpret_cast<const ulonglong2*>(&ws[(k4 * 4 + c) * D]);
#pragma unroll
            for (int j4 = 0; j4 < 16; j4++) {
                ulonglong2 w = wr[j4];
                fma2(acc[2 * j4],     a, w.x);
                fma2(acc[2 * j4 + 1], a, w.y);
            }
        }
    }
    float* out = (half ? g_Q : g_P) + (size_t)v * D;
    u64* o64 = reinterpret_cast<u64*>(out);
#pragma unroll
    for (int j = 0; j < 32; j++) o64[j] = acc[j];
}

// ---------------- edge pass over dst-sorted edges ----------------
// Warp processes EPW consecutive sorted edges; accumulates relu'd messages in
// registers across runs of equal dst; one red.global.add.v2 per run.
#define EPW 16
__global__ void __launch_bounds__(256) edge_kernel(const float* __restrict__ eattr,
                                                   const float* __restrict__ msg_w,
                                                   int l, int E) {
    const float* W = msg_w + (size_t)l * MSG_IN * D + (size_t)128 * D;
    const int lane = threadIdx.x & 31;
    const int gwarp = (blockIdx.x * 256 + threadIdx.x) >> 5;

    u64 Wreg[16];
#pragma unroll
    for (int k = 0; k < 16; k++)
        Wreg[k] = *reinterpret_cast<const u64*>(W + k * D + 2 * lane);

    const int e0 = gwarp * EPW;
    if (e0 >= E) return;
    const int eend = (e0 + EPW < E) ? e0 + EPW : E;

    int cur = -1;
    u64 accv = 0ULL, pv = 0ULL;

    for (int e = e0; e < eend; e++) {
        const int dst = g_sdst[e];
        const int src = g_ssrc[e];
        const int eo  = g_eord[e];

        if (dst != cur) {
            if (cur >= 0) {
                float lo, hi; unpack2(accv, lo, hi);
                asm volatile("red.global.add.v2.f32 [%0], {%1,%2};"
                             :: "l"(g_agg + (size_t)cur * D + 2 * lane), "f"(lo), "f"(hi)
                             : "memory");
            }
            cur = dst;
            accv = 0ULL;
            pv = *reinterpret_cast<const u64*>(g_P + (size_t)dst * D + 2 * lane);
        }

        const u64 q = *reinterpret_cast<const u64*>(g_Q + (size_t)src * D + 2 * lane);
        float myea = 0.f;
        if (lane < EDGE_DIM) myea = eattr[(size_t)eo * EDGE_DIM + lane];

        u64 m0 = add2(pv, q);
        u64 m1 = 0ULL;
#pragma unroll
        for (int k = 0; k < EDGE_DIM; k += 2) {
            float s0 = __shfl_sync(0xffffffffu, myea, k);
            float s1 = __shfl_sync(0xffffffffu, myea, k + 1);
            fma2(m0, pack2(s0, s0), Wreg[k]);
            fma2(m1, pack2(s1, s1), Wreg[k + 1]);
        }
        m0 = add2(m0, m1);
        float lo, hi; unpack2(m0, lo, hi);
        lo = fmaxf(lo, 0.f);
        hi = fmaxf(hi, 0.f);
        accv = add2(accv, pack2(lo, hi));
    }
    if (cur >= 0) {
        float lo, hi; unpack2(accv, lo, hi);
        asm volatile("red.global.add.v2.f32 [%0], {%1,%2};"
                     :: "l"(g_agg + (size_t)cur * D + 2 * lane), "f"(lo), "f"(hi)
                     : "memory");
    }
}

// ---------------- node update (1 thread/node) ----------------
__global__ void upd_kernel(const float* __restrict__ xin,
                           const float* __restrict__ upd_w,
                           const float* __restrict__ upd_b,
                           int l, int N, float* __restrict__ xout) {
    __shared__ __align__(16) float ws[UPD_IN * D];   // 32 KB
    __shared__ __align__(16) float bs[D];
    const float* x_src = xin ? xin : g_x;
    float* x_dst = xout ? xout : g_x;
    const float* W = upd_w + (size_t)l * UPD_IN * D;
    for (int i = threadIdx.x; i < UPD_IN * D; i += 256) ws[i] = W[i];
    if (threadIdx.x < D) bs[threadIdx.x] = upd_b[l * D + threadIdx.x];
    __syncthreads();

    int v = blockIdx.x * 256 + threadIdx.x;
    if (v >= N) return;

    u64 acc[32];
    const u64* bp = reinterpret_cast<const u64*>(bs);
#pragma unroll
    for (int j = 0; j < 32; j++) acc[j] = bp[j];

    const float4* xr = reinterpret_cast<const float4*>(x_src + (size_t)v * D);
    const float4* ar = reinterpret_cast<const float4*>(g_agg + (size_t)v * D);

    for (int k4 = 0; k4 < 16; k4++) {
        float4 xv = xr[k4];
#pragma unroll
        for (int c = 0; c < 4; c++) {
            float xs = (c == 0) ? xv.x : (c == 1) ? xv.y : (c == 2) ? xv.z : xv.w;
            u64 a = pack2(xs, xs);
            const ulonglong2* wr = reinterpret_cast<const ulonglong2*>(&ws[(k4 * 4 + c) * D]);
#pragma unroll
            for (int j4 = 0; j4 < 16; j4++) {
                ulonglong2 w = wr[j4];
                fma2(acc[2 * j4],     a, w.x);
                fma2(acc[2 * j4 + 1], a, w.y);
            }
        }
    }
    for (int k4 = 0; k4 < 16; k4++) {
        float4 av = ar[k4];
#pragma unroll
        for (int c = 0; c < 4; c++) {
            float xs = (c == 0) ? av.x : (c == 1) ? av.y : (c == 2) ? av.z : av.w;
            u64 a = pack2(xs, xs);
            const ulonglong2* wr = reinterpret_cast<const ulonglong2*>(&ws[(64 + k4 * 4 + c) * D]);
#pragma unroll
            for (int j4 = 0; j4 < 16; j4++) {
                ulonglong2 w = wr[j4];
                fma2(acc[2 * j4],     a, w.x);
                fma2(acc[2 * j4 + 1], a, w.y);
            }
        }
    }

    float* o = x_dst + (size_t)v * D;
#pragma unroll
    for (int j = 0; j < 32; j++) {
        float lo, hi;
        unpack2(acc[j], lo, hi);
        float2 rv;
        rv.x = fmaxf(lo, 0.f);
        rv.y = fmaxf(hi, 0.f);
        *reinterpret_cast<float2*>(&o[2 * j]) = rv;
    }
}

// ---------------- launcher ----------------
extern "C" void kernel_launch(void* const* d_in, const int* in_sizes, int n_in,
                              void* d_out, int out_size) {
    const float* x      = (const float*)d_in[0];
    const void*  eidx   = d_in[1];
    const float* eattr  = (const float*)d_in[2];
    const float* msg_w  = (const float*)d_in[3];
    const float* msg_b  = (const float*)d_in[4];
    const float* upd_w  = (const float*)d_in[5];
    const float* upd_b  = (const float*)d_in[6];

    const int N = in_sizes[0] / D;
    const int E = in_sizes[2] / EDGE_DIM;
    const int L = in_sizes[4] / D;

    const int nB = (N + 255) / 256;
    const int eB = (E + 255) / 256;
    const int scanB = (N + SCAN_B - 1) / SCAN_B;

    // ---- one-time: detect index width + counting sort edges by dst ----
    detect_kernel<<<1, 256>>>((const unsigned int*)eidx);
    zero_cnt_kernel<<<nB, 256>>>(N);
    hist_kernel<<<eB, 256>>>(eidx, E);
    scan1_kernel<<<scanB, SCAN_B>>>(N);
    scan2_kernel<<<1, 64>>>(scanB);
    scan3_kernel<<<nB, 256>>>(N);
    scatter_kernel<<<eB, 256>>>(eidx, E);

    const int node_blocks = nB;
    const int edge_blocks = (E + 8 * EPW - 1) / (8 * EPW);

    for (int l = 0; l < L; l++) {
        const float* xin = (l == 0) ? x : nullptr;            // nullptr -> g_x
        float* xout = (l == L - 1) ? (float*)d_out : nullptr; // nullptr -> g_x

        dim3 pq_grid(node_blocks, 2);
        pq_kernel<<<pq_grid, 256>>>(xin, msg_w, msg_b, l, N);
        edge_kernel<<<edge_blocks, 256>>>(eattr, msg_w, l, E);
        upd_kernel<<<node_blocks, 256>>>(xin, upd_w, upd_b, l, N, xout);
    }
}

// round 10
// speedup vs baseline: 1.1124x; 1.1124x over previous
#include <cuda_runtime.h>
#include <cstdint>

#define D         64
#define EDGE_DIM  16
#define MSG_IN    144
#define UPD_IN    128
#define MAXN      50000
#define MAXE      800000
#define SCAN_B    1024

// ---------------- scratch (device globals; no allocation allowed) ----------------
__device__ __align__(256) float g_x[MAXN * D];
__device__ __align__(256) float g_P[MAXN * D];   // x @ W_i + msg_b  (dst side)
__device__ __align__(256) float g_Q[MAXN * D];   // x @ W_j          (src side)
__device__ __align__(256) float g_agg[MAXN * D];
__device__ __align__(256) float g_eas[(size_t)MAXE * EDGE_DIM];  // eattr, dst-sorted
__device__ int g_ssrc[MAXE];     // src, sorted by dst
__device__ int g_sdst[MAXE];     // dst, sorted (ascending groups)
__device__ int g_eord[MAXE];     // original edge id, sorted by dst (used once, for permute)
__device__ int g_cnt[MAXN];      // per-dst degree
__device__ int g_incl[MAXN];     // inclusive scan within blocks
__device__ int g_pos[MAXN];      // running scatter cursor
__device__ int g_bsum[64];
__device__ int g_bsumx[64];
__device__ int g_is64;

typedef unsigned long long u64;

// ---------------- packed f32x2 helpers ----------------
__device__ __forceinline__ u64 pack2(float lo, float hi) {
    u64 r; asm("mov.b64 %0, {%1,%2};" : "=l"(r) : "f"(lo), "f"(hi)); return r;
}
__device__ __forceinline__ void fma2(u64& acc, u64 a, u64 b) {
    asm("fma.rn.f32x2 %0, %1, %2, %0;" : "+l"(acc) : "l"(a), "l"(b));
}
__device__ __forceinline__ u64 add2(u64 a, u64 b) {
    u64 r; asm("add.rn.f32x2 %0, %1, %2;" : "=l"(r) : "l"(a), "l"(b)); return r;
}
__device__ __forceinline__ void unpack2(u64 v, float& lo, float& hi) {
    asm("mov.b64 {%0,%1}, %2;" : "=f"(lo), "=f"(hi) : "l"(v));
}

// ---------------- dtype sniffing ----------------
__global__ void detect_kernel(const unsigned int* __restrict__ idx) {
    __shared__ unsigned int acc[256];
    unsigned int v = 0;
    for (int i = threadIdx.x; i < 2048; i += 256) v |= idx[2 * i + 1];
    acc[threadIdx.x] = v;
    __syncthreads();
    for (int s = 128; s > 0; s >>= 1) {
        if (threadIdx.x < s) acc[threadIdx.x] |= acc[threadIdx.x + s];
        __syncthreads();
    }
    if (threadIdx.x == 0) g_is64 = (acc[0] == 0u) ? 1 : 0;
}

// ---------------- zero counters ----------------
__global__ void zero_cnt_kernel(int N) {
    int i = blockIdx.x * 256 + threadIdx.x;
    if (i < N) g_cnt[i] = 0;
    if (blockIdx.x == 0 && threadIdx.x < 64) g_bsum[threadIdx.x] = 0;
}

// ---------------- histogram of dst ----------------
__global__ void hist_kernel(const void* __restrict__ eidx, int E) {
    int i = blockIdx.x * 256 + threadIdx.x;
    if (i >= E) return;
    int dst;
    if (g_is64) dst = (int)reinterpret_cast<const long long*>(eidx)[(size_t)E + i];
    else        dst = reinterpret_cast<const int*>(eidx)[E + i];
    atomicAdd(&g_cnt[dst], 1);
}

// ---------------- scan stage 1: per-block inclusive scan ----------------
__global__ void scan1_kernel(int N) {
    __shared__ int s[SCAN_B];
    int tid = threadIdx.x;
    int i = blockIdx.x * SCAN_B + tid;
    int v = (i < N) ? g_cnt[i] : 0;
    s[tid] = v;
    __syncthreads();
    for (int off = 1; off < SCAN_B; off <<= 1) {
        int t = (tid >= off) ? s[tid - off] : 0;
        __syncthreads();
        s[tid] += t;
        __syncthreads();
    }
    if (i < N) g_incl[i] = s[tid];
    if (tid == SCAN_B - 1) g_bsum[blockIdx.x] = s[tid];
}

// ---------------- scan stage 2: exclusive scan of block sums ----------------
__global__ void scan2_kernel(int nb) {
    __shared__ int s[64];
    int tid = threadIdx.x;
    s[tid] = (tid < nb) ? g_bsum[tid] : 0;
    __syncthreads();
    if (tid == 0) {
        int run = 0;
        for (int b = 0; b < nb; b++) { g_bsumx[b] = run; run += s[b]; }
    }
}

// ---------------- scan stage 3: start offsets into g_pos ----------------
__global__ void scan3_kernel(int N) {
    int i = blockIdx.x * 256 + threadIdx.x;
    if (i < N) g_pos[i] = g_incl[i] + g_bsumx[i / SCAN_B] - g_cnt[i];
}

// ---------------- scatter: build dst-sorted edge arrays ----------------
__global__ void scatter_kernel(const void* __restrict__ eidx, int E) {
    int i = blockIdx.x * 256 + threadIdx.x;
    if (i >= E) return;
    int src, dst;
    if (g_is64) {
        const long long* p = reinterpret_cast<const long long*>(eidx);
        src = (int)p[i];
        dst = (int)p[(size_t)E + i];
    } else {
        const int* p = reinterpret_cast<const int*>(eidx);
        src = p[i];
        dst = p[E + i];
    }
    int pos = atomicAdd(&g_pos[dst], 1);
    g_ssrc[pos] = src;
    g_sdst[pos] = dst;
    g_eord[pos] = i;
}

// ---------------- permute eattr into dst-sorted order (once) ----------------
// 4 threads per edge, one float4 each: coalesced stores, random 64B-granule loads.
__global__ void permute_ea_kernel(const float* __restrict__ eattr, int E) {
    int gt = blockIdx.x * 256 + threadIdx.x;
    int e = gt >> 2;
    if (e >= E) return;
    int c = gt & 3;
    int eo = g_eord[e];
    float4 v = reinterpret_cast<const float4*>(eattr + (size_t)eo * EDGE_DIM)[c];
    reinterpret_cast<float4*>(g_eas + (size_t)e * EDGE_DIM)[c] = v;
}

// ---------------- P/Q precompute (1 thread/node, 64 accumulators; zeroes agg) ----------------
__global__ void pq_kernel(const float* __restrict__ xin,
                          const float* __restrict__ msg_w,
                          const float* __restrict__ msg_b,
                          int l, int N) {
    __shared__ __align__(16) float ws[64 * D];   // 16 KB
    __shared__ __align__(16) float bs[D];
    const int half = blockIdx.y;
    const float* x_src = xin ? xin : g_x;
    const float* W = msg_w + (size_t)l * MSG_IN * D + (size_t)half * 64 * D;
    for (int i = threadIdx.x; i < 64 * D; i += 256) ws[i] = W[i];
    if (threadIdx.x < D) bs[threadIdx.x] = half ? 0.f : msg_b[l * D + threadIdx.x];
    __syncthreads();

    int v = blockIdx.x * 256 + threadIdx.x;
    if (v >= N) return;

    if (half == 0) {   // zero agg rows for this layer
        float4 z = make_float4(0.f, 0.f, 0.f, 0.f);
        float4* ap = reinterpret_cast<float4*>(g_agg + (size_t)v * D);
#pragma unroll
        for (int j = 0; j < 16; j++) ap[j] = z;
    }

    u64 acc[32];
    const u64* bp = reinterpret_cast<const u64*>(bs);
#pragma unroll
    for (int j = 0; j < 32; j++) acc[j] = bp[j];

    const float4* xr = reinterpret_cast<const float4*>(x_src + (size_t)v * D);
    for (int k4 = 0; k4 < 16; k4++) {
        float4 xv = xr[k4];
#pragma unroll
        for (int c = 0; c < 4; c++) {
            float xs = (c == 0) ? xv.x : (c == 1) ? xv.y : (c == 2) ? xv.z : xv.w;
            u64 a = pack2(xs, xs);
            const ulonglong2* wr = reinterpret_cast<const ulonglong2*>(&ws[(k4 * 4 + c) * D]);
#pragma unroll
            for (int j4 = 0; j4 < 16; j4++) {
                ulonglong2 w = wr[j4];
                fma2(acc[2 * j4],     a, w.x);
                fma2(acc[2 * j4 + 1], a, w.y);
            }
        }
    }
    float* out = (half ? g_Q : g_P) + (size_t)v * D;
    u64* o64 = reinterpret_cast<u64*>(out);
#pragma unroll
    for (int j = 0; j < 32; j++) o64[j] = acc[j];
}

// ---------------- edge pass over dst-sorted edges (sequential eattr) ----------------
#define EPW 16
__global__ void __launch_bounds__(256) edge_kernel(const float* __restrict__ msg_w,
                                                   int l, int E) {
    const float* W = msg_w + (size_t)l * MSG_IN * D + (size_t)128 * D;
    const int lane = threadIdx.x & 31;
    const int gwarp = (blockIdx.x * 256 + threadIdx.x) >> 5;

    u64 Wreg[16];
#pragma unroll
    for (int k = 0; k < 16; k++)
        Wreg[k] = *reinterpret_cast<const u64*>(W + k * D + 2 * lane);

    const int e0 = gwarp * EPW;
    if (e0 >= E) return;
    const int eend = (e0 + EPW < E) ? e0 + EPW : E;

    int cur = -1;
    u64 accv = 0ULL, pv = 0ULL;

    for (int e = e0; e < eend; e++) {
        const int dst = g_sdst[e];
        const int src = g_ssrc[e];

        if (dst != cur) {
            if (cur >= 0) {
                float lo, hi; unpack2(accv, lo, hi);
                asm volatile("red.global.add.v2.f32 [%0], {%1,%2};"
                             :: "l"(g_agg + (size_t)cur * D + 2 * lane), "f"(lo), "f"(hi)
                             : "memory");
            }
            cur = dst;
            accv = 0ULL;
            pv = *reinterpret_cast<const u64*>(g_P + (size_t)dst * D + 2 * lane);
        }

        const u64 q = *reinterpret_cast<const u64*>(g_Q + (size_t)src * D + 2 * lane);
        float myea = 0.f;
        if (lane < EDGE_DIM) myea = g_eas[(size_t)e * EDGE_DIM + lane];

        u64 m0 = add2(pv, q);
        u64 m1 = 0ULL;
#pragma unroll
        for (int k = 0; k < EDGE_DIM; k += 2) {
            float s0 = __shfl_sync(0xffffffffu, myea, k);
            float s1 = __shfl_sync(0xffffffffu, myea, k + 1);
            fma2(m0, pack2(s0, s0), Wreg[k]);
            fma2(m1, pack2(s1, s1), Wreg[k + 1]);
        }
        m0 = add2(m0, m1);
        float lo, hi; unpack2(m0, lo, hi);
        lo = fmaxf(lo, 0.f);
        hi = fmaxf(hi, 0.f);
        accv = add2(accv, pack2(lo, hi));
    }
    if (cur >= 0) {
        float lo, hi; unpack2(accv, lo, hi);
        asm volatile("red.global.add.v2.f32 [%0], {%1,%2};"
                     :: "l"(g_agg + (size_t)cur * D + 2 * lane), "f"(lo), "f"(hi)
                     : "memory");
    }
}

// ---------------- node update (1 thread/node) ----------------
__global__ void upd_kernel(const float* __restrict__ xin,
                           const float* __restrict__ upd_w,
                           const float* __restrict__ upd_b,
                           int l, int N, float* __restrict__ xout) {
    __shared__ __align__(16) float ws[UPD_IN * D];   // 32 KB
    __shared__ __align__(16) float bs[D];
    const float* x_src = xin ? xin : g_x;
    float* x_dst = xout ? xout : g_x;
    const float* W = upd_w + (size_t)l * UPD_IN * D;
    for (int i = threadIdx.x; i < UPD_IN * D; i += 256) ws[i] = W[i];
    if (threadIdx.x < D) bs[threadIdx.x] = upd_b[l * D + threadIdx.x];
    __syncthreads();

    int v = blockIdx.x * 256 + threadIdx.x;
    if (v >= N) return;

    u64 acc[32];
    const u64* bp = reinterpret_cast<const u64*>(bs);
#pragma unroll
    for (int j = 0; j < 32; j++) acc[j] = bp[j];

    const float4* xr = reinterpret_cast<const float4*>(x_src + (size_t)v * D);
    const float4* ar = reinterpret_cast<const float4*>(g_agg + (size_t)v * D);

    for (int k4 = 0; k4 < 16; k4++) {
        float4 xv = xr[k4];
#pragma unroll
        for (int c = 0; c < 4; c++) {
            float xs = (c == 0) ? xv.x : (c == 1) ? xv.y : (c == 2) ? xv.z : xv.w;
            u64 a = pack2(xs, xs);
            const ulonglong2* wr = reinterpret_cast<const ulonglong2*>(&ws[(k4 * 4 + c) * D]);
#pragma unroll
            for (int j4 = 0; j4 < 16; j4++) {
                ulonglong2 w = wr[j4];
                fma2(acc[2 * j4],     a, w.x);
                fma2(acc[2 * j4 + 1], a, w.y);
            }
        }
    }
    for (int k4 = 0; k4 < 16; k4++) {
        float4 av = ar[k4];
#pragma unroll
        for (int c = 0; c < 4; c++) {
            float xs = (c == 0) ? av.x : (c == 1) ? av.y : (c == 2) ? av.z : av.w;
            u64 a = pack2(xs, xs);
            const ulonglong2* wr = reinterpret_cast<const ulonglong2*>(&ws[(64 + k4 * 4 + c) * D]);
#pragma unroll
            for (int j4 = 0; j4 < 16; j4++) {
                ulonglong2 w = wr[j4];
                fma2(acc[2 * j4],     a, w.x);
                fma2(acc[2 * j4 + 1], a, w.y);
            }
        }
    }

    float* o = x_dst + (size_t)v * D;
#pragma unroll
    for (int j = 0; j < 32; j++) {
        float lo, hi;
        unpack2(acc[j], lo, hi);
        float2 rv;
        rv.x = fmaxf(lo, 0.f);
        rv.y = fmaxf(hi, 0.f);
        *reinterpret_cast<float2*>(&o[2 * j]) = rv;
    }
}

// ---------------- launcher ----------------
extern "C" void kernel_launch(void* const* d_in, const int* in_sizes, int n_in,
                              void* d_out, int out_size) {
    const float* x      = (const float*)d_in[0];
    const void*  eidx   = d_in[1];
    const float* eattr  = (const float*)d_in[2];
    const float* msg_w  = (const float*)d_in[3];
    const float* msg_b  = (const float*)d_in[4];
    const float* upd_w  = (const float*)d_in[5];
    const float* upd_b  = (const float*)d_in[6];

    const int N = in_sizes[0] / D;
    const int E = in_sizes[2] / EDGE_DIM;
    const int L = in_sizes[4] / D;

    const int nB = (N + 255) / 256;
    const int eB = (E + 255) / 256;
    const int scanB = (N + SCAN_B - 1) / SCAN_B;

    // ---- one-time: detect index width, counting-sort edges by dst, permute eattr ----
    detect_kernel<<<1, 256>>>((const unsigned int*)eidx);
    zero_cnt_kernel<<<nB, 256>>>(N);
    hist_kernel<<<eB, 256>>>(eidx, E);
    scan1_kernel<<<scanB, SCAN_B>>>(N);
    scan2_kernel<<<1, 64>>>(scanB);
    scan3_kernel<<<nB, 256>>>(N);
    scatter_kernel<<<eB, 256>>>(eidx, E);
    permute_ea_kernel<<<(4 * E + 255) / 256, 256>>>(eattr, E);

    const int node_blocks = nB;
    const int edge_blocks = (E + 8 * EPW - 1) / (8 * EPW);

    for (int l = 0; l < L; l++) {
        const float* xin = (l == 0) ? x : nullptr;            // nullptr -> g_x
        float* xout = (l == L - 1) ? (float*)d_out : nullptr; // nullptr -> g_x

        dim3 pq_grid(node_blocks, 2);
        pq_kernel<<<pq_grid, 256>>>(xin, msg_w, msg_b, l, N);
        edge_kernel<<<edge_blocks, 256>>>(msg_w, l, E);
        upd_kernel<<<node_blocks, 256>>>(xin, upd_w, upd_b, l, N, xout);
    }
}

// round 11
// speedup vs baseline: 1.1309x; 1.0166x over previous
#include <cuda_runtime.h>
#include <cstdint>

#define D         64
#define EDGE_DIM  16
#define MSG_IN    144
#define UPD_IN    128
#define MAXN      50000
#define MAXE      800000
#define SCAN_B    1024

// ---------------- scratch (device globals; no allocation allowed) ----------------
__device__ __align__(256) float g_x[MAXN * D];
__device__ __align__(256) float g_P[MAXN * D];   // x @ W_i + msg_b  (dst side)
__device__ __align__(256) float g_Q[MAXN * D];   // x @ W_j          (src side)
__device__ __align__(256) float g_agg[MAXN * D];
__device__ __align__(256) float g_eas[(size_t)MAXE * EDGE_DIM];  // eattr, CSR order
__device__ int g_ssrc[MAXE];        // src, CSR order (grouped by dst)
__device__ int g_eord[MAXE];        // original edge id, CSR order (permute only)
__device__ int g_row[MAXN + 1];     // CSR row offsets per dst
__device__ int g_cnt[MAXN];         // per-dst degree
__device__ int g_incl[MAXN];        // inclusive scan within blocks
__device__ int g_pos[MAXN];         // scatter cursor
__device__ int g_bsum[64];
__device__ int g_bsumx[64];
__device__ int g_is64;

typedef unsigned long long u64;

// ---------------- packed f32x2 helpers ----------------
__device__ __forceinline__ u64 pack2(float lo, float hi) {
    u64 r; asm("mov.b64 %0, {%1,%2};" : "=l"(r) : "f"(lo), "f"(hi)); return r;
}
__device__ __forceinline__ void fma2(u64& acc, u64 a, u64 b) {
    asm("fma.rn.f32x2 %0, %1, %2, %0;" : "+l"(acc) : "l"(a), "l"(b));
}
__device__ __forceinline__ u64 add2(u64 a, u64 b) {
    u64 r; asm("add.rn.f32x2 %0, %1, %2;" : "=l"(r) : "l"(a), "l"(b)); return r;
}
__device__ __forceinline__ void unpack2(u64 v, float& lo, float& hi) {
    asm("mov.b64 {%0,%1}, %2;" : "=f"(lo), "=f"(hi) : "l"(v));
}

// ---------------- dtype sniffing ----------------
__global__ void detect_kernel(const unsigned int* __restrict__ idx) {
    __shared__ unsigned int acc[256];
    unsigned int v = 0;
    for (int i = threadIdx.x; i < 2048; i += 256) v |= idx[2 * i + 1];
    acc[threadIdx.x] = v;
    __syncthreads();
    for (int s = 128; s > 0; s >>= 1) {
        if (threadIdx.x < s) acc[threadIdx.x] |= acc[threadIdx.x + s];
        __syncthreads();
    }
    if (threadIdx.x == 0) g_is64 = (acc[0] == 0u) ? 1 : 0;
}

// ---------------- zero counters ----------------
__global__ void zero_cnt_kernel(int N) {
    int i = blockIdx.x * 256 + threadIdx.x;
    if (i < N) g_cnt[i] = 0;
    if (blockIdx.x == 0 && threadIdx.x < 64) g_bsum[threadIdx.x] = 0;
}

// ---------------- histogram of dst ----------------
__global__ void hist_kernel(const void* __restrict__ eidx, int E) {
    int i = blockIdx.x * 256 + threadIdx.x;
    if (i >= E) return;
    int dst;
    if (g_is64) dst = (int)reinterpret_cast<const long long*>(eidx)[(size_t)E + i];
    else        dst = reinterpret_cast<const int*>(eidx)[E + i];
    atomicAdd(&g_cnt[dst], 1);
}

// ---------------- scan stage 1: per-block inclusive scan ----------------
__global__ void scan1_kernel(int N) {
    __shared__ int s[SCAN_B];
    int tid = threadIdx.x;
    int i = blockIdx.x * SCAN_B + tid;
    int v = (i < N) ? g_cnt[i] : 0;
    s[tid] = v;
    __syncthreads();
    for (int off = 1; off < SCAN_B; off <<= 1) {
        int t = (tid >= off) ? s[tid - off] : 0;
        __syncthreads();
        s[tid] += t;
        __syncthreads();
    }
    if (i < N) g_incl[i] = s[tid];
    if (tid == SCAN_B - 1) g_bsum[blockIdx.x] = s[tid];
}

// ---------------- scan stage 2: exclusive scan of block sums ----------------
__global__ void scan2_kernel(int nb) {
    __shared__ int s[64];
    int tid = threadIdx.x;
    s[tid] = (tid < nb) ? g_bsum[tid] : 0;
    __syncthreads();
    if (tid == 0) {
        int run = 0;
        for (int b = 0; b < nb; b++) { g_bsumx[b] = run; run += s[b]; }
    }
}

// ---------------- scan stage 3: CSR row starts + scatter cursors ----------------
__global__ void scan3_kernel(int N, int E) {
    int i = blockIdx.x * 256 + threadIdx.x;
    if (i < N) {
        int start = g_incl[i] + g_bsumx[i / SCAN_B] - g_cnt[i];
        g_row[i] = start;
        g_pos[i] = start;
    }
    if (i == 0) g_row[N] = E;
}

// ---------------- scatter: build CSR edge arrays (src + original id) ----------------
__global__ void scatter_kernel(const void* __restrict__ eidx, int E) {
    int i = blockIdx.x * 256 + threadIdx.x;
    if (i >= E) return;
    int src, dst;
    if (g_is64) {
        const long long* p = reinterpret_cast<const long long*>(eidx);
        src = (int)p[i];
        dst = (int)p[(size_t)E + i];
    } else {
        const int* p = reinterpret_cast<const int*>(eidx);
        src = p[i];
        dst = p[E + i];
    }
    int pos = atomicAdd(&g_pos[dst], 1);
    g_ssrc[pos] = src;
    g_eord[pos] = i;
}

// ---------------- permute eattr into CSR order (once per launch) ----------------
__global__ void permute_ea_kernel(const float* __restrict__ eattr, int E) {
    int gt = blockIdx.x * 256 + threadIdx.x;
    int e = gt >> 2;
    if (e >= E) return;
    int c = gt & 3;
    int eo = g_eord[e];
    float4 v = reinterpret_cast<const float4*>(eattr + (size_t)eo * EDGE_DIM)[c];
    reinterpret_cast<float4*>(g_eas + (size_t)e * EDGE_DIM)[c] = v;
}

// ---------------- P/Q precompute (1 thread/node, 64 accumulators) ----------------
__global__ void pq_kernel(const float* __restrict__ xin,
                          const float* __restrict__ msg_w,
                          const float* __restrict__ msg_b,
                          int l, int N) {
    __shared__ __align__(16) float ws[64 * D];   // 16 KB
    __shared__ __align__(16) float bs[D];
    const int half = blockIdx.y;
    const float* x_src = xin ? xin : g_x;
    const float* W = msg_w + (size_t)l * MSG_IN * D + (size_t)half * 64 * D;
    for (int i = threadIdx.x; i < 64 * D; i += 256) ws[i] = W[i];
    if (threadIdx.x < D) bs[threadIdx.x] = half ? 0.f : msg_b[l * D + threadIdx.x];
    __syncthreads();

    int v = blockIdx.x * 256 + threadIdx.x;
    if (v >= N) return;

    u64 acc[32];
    const u64* bp = reinterpret_cast<const u64*>(bs);
#pragma unroll
    for (int j = 0; j < 32; j++) acc[j] = bp[j];

    const float4* xr = reinterpret_cast<const float4*>(x_src + (size_t)v * D);
    for (int k4 = 0; k4 < 16; k4++) {
        float4 xv = xr[k4];
#pragma unroll
        for (int c = 0; c < 4; c++) {
            float xs = (c == 0) ? xv.x : (c == 1) ? xv.y : (c == 2) ? xv.z : xv.w;
            u64 a = pack2(xs, xs);
            const ulonglong2* wr = reinterpret_cast<const ulonglong2*>(&ws[(k4 * 4 + c) * D]);
#pragma unroll
            for (int j4 = 0; j4 < 16; j4++) {
                ulonglong2 w = wr[j4];
                fma2(acc[2 * j4],     a, w.x);
                fma2(acc[2 * j4 + 1], a, w.y);
            }
        }
    }
    float* out = (half ? g_Q : g_P) + (size_t)v * D;
    u64* o64 = reinterpret_cast<u64*>(out);
#pragma unroll
    for (int j = 0; j < 32; j++) o64[j] = acc[j];
}

// ---------------- edge pass: CSR warp-per-node, no atomics ----------------
// Warp owns dst node v: agg[v] = sum_e relu(P[v] + Q[src_e] + ea_e @ W_e),
// accumulated in registers, one plain 8B store per lane at the end.
__global__ void __launch_bounds__(256) edge_kernel(const float* __restrict__ msg_w,
                                                   int l, int N) {
    const float* W = msg_w + (size_t)l * MSG_IN * D + (size_t)128 * D;
    const int lane = threadIdx.x & 31;
    const int v = (blockIdx.x * 256 + threadIdx.x) >> 5;

    u64 Wreg[16];
#pragma unroll
    for (int k = 0; k < 16; k++)
        Wreg[k] = *reinterpret_cast<const u64*>(W + k * D + 2 * lane);

    if (v >= N) return;
    const int e0 = g_row[v];
    const int e1 = g_row[v + 1];

    u64 accv = 0ULL;
    if (e0 < e1) {
        const u64 pv = *reinterpret_cast<const u64*>(g_P + (size_t)v * D + 2 * lane);
        for (int e = e0; e < e1; e++) {
            const int src = g_ssrc[e];
            const u64 q = *reinterpret_cast<const u64*>(g_Q + (size_t)src * D + 2 * lane);
            float myea = 0.f;
            if (lane < EDGE_DIM) myea = g_eas[(size_t)e * EDGE_DIM + lane];

            u64 m0 = add2(pv, q);
            u64 m1 = 0ULL;
#pragma unroll
            for (int k = 0; k < EDGE_DIM; k += 2) {
                float s0 = __shfl_sync(0xffffffffu, myea, k);
                float s1 = __shfl_sync(0xffffffffu, myea, k + 1);
                fma2(m0, pack2(s0, s0), Wreg[k]);
                fma2(m1, pack2(s1, s1), Wreg[k + 1]);
            }
            m0 = add2(m0, m1);
            float lo, hi; unpack2(m0, lo, hi);
            lo = fmaxf(lo, 0.f);
            hi = fmaxf(hi, 0.f);
            accv = add2(accv, pack2(lo, hi));
        }
    }
    *reinterpret_cast<u64*>(g_agg + (size_t)v * D + 2 * lane) = accv;
}

// ---------------- node update (1 thread/node) ----------------
__global__ void upd_kernel(const float* __restrict__ xin,
                           const float* __restrict__ upd_w,
                           const float* __restrict__ upd_b,
                           int l, int N, float* __restrict__ xout) {
    __shared__ __align__(16) float ws[UPD_IN * D];   // 32 KB
    __shared__ __align__(16) float bs[D];
    const float* x_src = xin ? xin : g_x;
    float* x_dst = xout ? xout : g_x;
    const float* W = upd_w + (size_t)l * UPD_IN * D;
    for (int i = threadIdx.x; i < UPD_IN * D; i += 256) ws[i] = W[i];
    if (threadIdx.x < D) bs[threadIdx.x] = upd_b[l * D + threadIdx.x];
    __syncthreads();

    int v = blockIdx.x * 256 + threadIdx.x;
    if (v >= N) return;

    u64 acc[32];
    const u64* bp = reinterpret_cast<const u64*>(bs);
#pragma unroll
    for (int j = 0; j < 32; j++) acc[j] = bp[j];

    const float4* xr = reinterpret_cast<const float4*>(x_src + (size_t)v * D);
    const float4* ar = reinterpret_cast<const float4*>(g_agg + (size_t)v * D);

    for (int k4 = 0; k4 < 16; k4++) {
        float4 xv = xr[k4];
#pragma unroll
        for (int c = 0; c < 4; c++) {
            float xs = (c == 0) ? xv.x : (c == 1) ? xv.y : (c == 2) ? xv.z : xv.w;
            u64 a = pack2(xs, xs);
            const ulonglong2* wr = reinterpret_cast<const ulonglong2*>(&ws[(k4 * 4 + c) * D]);
#pragma unroll
            for (int j4 = 0; j4 < 16; j4++) {
                ulonglong2 w = wr[j4];
                fma2(acc[2 * j4],     a, w.x);
                fma2(acc[2 * j4 + 1], a, w.y);
            }
        }
    }
    for (int k4 = 0; k4 < 16; k4++) {
        float4 av = ar[k4];
#pragma unroll
        for (int c = 0; c < 4; c++) {
            float xs = (c == 0) ? av.x : (c == 1) ? av.y : (c == 2) ? av.z : av.w;
            u64 a = pack2(xs, xs);
            const ulonglong2* wr = reinterpret_cast<const ulonglong2*>(&ws[(64 + k4 * 4 + c) * D]);
#pragma unroll
            for (int j4 = 0; j4 < 16; j4++) {
                ulonglong2 w = wr[j4];
                fma2(acc[2 * j4],     a, w.x);
                fma2(acc[2 * j4 + 1], a, w.y);
            }
        }
    }

    float* o = x_dst + (size_t)v * D;
#pragma unroll
    for (int j = 0; j < 32; j++) {
        float lo, hi;
        unpack2(acc[j], lo, hi);
        float2 rv;
        rv.x = fmaxf(lo, 0.f);
        rv.y = fmaxf(hi, 0.f);
        *reinterpret_cast<float2*>(&o[2 * j]) = rv;
    }
}

// ---------------- launcher ----------------
extern "C" void kernel_launch(void* const* d_in, const int* in_sizes, int n_in,
                              void* d_out, int out_size) {
    const float* x      = (const float*)d_in[0];
    const void*  eidx   = d_in[1];
    const float* eattr  = (const float*)d_in[2];
    const float* msg_w  = (const float*)d_in[3];
    const float* msg_b  = (const float*)d_in[4];
    const float* upd_w  = (const float*)d_in[5];
    const float* upd_b  = (const float*)d_in[6];

    const int N = in_sizes[0] / D;
    const int E = in_sizes[2] / EDGE_DIM;
    const int L = in_sizes[4] / D;

    const int nB = (N + 255) / 256;
    const int eB = (E + 255) / 256;
    const int scanB = (N + SCAN_B - 1) / SCAN_B;

    // ---- preprocessing (replayed each launch): CSR by dst + eattr permute ----
    detect_kernel<<<1, 256>>>((const unsigned int*)eidx);
    zero_cnt_kernel<<<nB, 256>>>(N);
    hist_kernel<<<eB, 256>>>(eidx, E);
    scan1_kernel<<<scanB, SCAN_B>>>(N);
    scan2_kernel<<<1, 64>>>(scanB);
    scan3_kernel<<<nB, 256>>>(N, E);
    scatter_kernel<<<eB, 256>>>(eidx, E);
    permute_ea_kernel<<<(4 * E + 255) / 256, 256>>>(eattr, E);

    const int node_blocks = nB;
    const int edge_blocks = (N + 7) / 8;   // 8 warps/block, warp per node

    for (int l = 0; l < L; l++) {
        const float* xin = (l == 0) ? x : nullptr;            // nullptr -> g_x
        float* xout = (l == L - 1) ? (float*)d_out : nullptr; // nullptr -> g_x

        dim3 pq_grid(node_blocks, 2);
        pq_kernel<<<pq_grid, 256>>>(xin, msg_w, msg_b, l, N);
        edge_kernel<<<edge_blocks, 256>>>(msg_w, l, N);
        upd_kernel<<<node_blocks, 256>>>(xin, upd_w, upd_b, l, N, xout);
    }
}